// round 12
// baseline (speedup 1.0000x reference)
#include <cuda_runtime.h>
#include <cuda_bf16.h>
#include <math.h>
#include <stdint.h>

constexpr int kD = 2048, kE = 32, kK = 8, kI = 1024, kMaxT = 8192;
constexpr int kMaxRows = kMaxT * kK;   // 65536

// ---------------- scratch (proven-size set; DO NOT grow) ----------------
__device__ int   g_topi[kMaxRows];
__device__ float g_topw[kMaxRows];
__device__ int   g_rowtok[kMaxRows];
__device__ float g_rowscale[kMaxRows];
__device__ int   g_counts[kE];
__device__ int   g_offsets[kE + 1];
__device__ int   g_cursor[kE];
__device__ float g_sumprob[kE];
__device__ int   g_flag;
__device__ __align__(16) float g_H[(size_t)kMaxRows * kI];   // 256 MB scratch

// ---------------- helpers ----------------
__device__ __forceinline__ void mma_bf16(float* c, const uint32_t* a, const uint32_t* b) {
    asm volatile(
        "mma.sync.aligned.m16n8k16.row.col.f32.bf16.bf16.f32 "
        "{%0,%1,%2,%3}, {%4,%5,%6,%7}, {%8,%9}, {%0,%1,%2,%3};"
        : "+f"(c[0]), "+f"(c[1]), "+f"(c[2]), "+f"(c[3])
        : "r"(a[0]), "r"(a[1]), "r"(a[2]), "r"(a[3]), "r"(b[0]), "r"(b[1]));
}
// Truncation-based hi/lo split of a float pair, packed as bf16x2.
__device__ __forceinline__ void pack2(float a, float b, uint32_t& hi, uint32_t& lo) {
    uint32_t ra = __float_as_uint(a), rb = __float_as_uint(b);
    asm("prmt.b32 %0, %1, %2, 0x7632;" : "=r"(hi) : "r"(ra), "r"(rb));
    float la = a - __uint_as_float(ra & 0xFFFF0000u);
    float lb = b - __uint_as_float(rb & 0xFFFF0000u);
    asm("prmt.b32 %0, %1, %2, 0x7632;" : "=r"(lo) : "r"(__float_as_uint(la)), "r"(__float_as_uint(lb)));
}

// ---------------- launch 1: zero out + reset bookkeeping ----------------
__global__ void zeroreset_kernel(float* __restrict__ out, size_t n) {
    size_t i = (size_t)blockIdx.x * blockDim.x + threadIdx.x;
    size_t stride = (size_t)gridDim.x * blockDim.x;
    for (; i < n; i += stride) out[i] = 0.f;
    if (blockIdx.x == 0) {
        if (threadIdx.x < kE) {
            g_counts[threadIdx.x] = 0;
            g_cursor[threadIdx.x] = 0;
            g_sumprob[threadIdx.x] = 0.f;
        }
        if (threadIdx.x == 0) g_flag = 0;
    }
}

// ---------------- launch 2: router ----------------
__global__ void router_kernel(const float* __restrict__ x,
                              const float* __restrict__ Wgate, int T) {
    int warp = (blockIdx.x * blockDim.x + threadIdx.x) >> 5;
    int lane = threadIdx.x & 31;
    if (warp >= T) return;
    const float* xt = x + (size_t)warp * kD;

    float acc = 0.f;
#pragma unroll 4
    for (int d = 0; d < kD; ++d) acc += xt[d] * Wgate[d * kE + lane];

    float m = acc;
#pragma unroll
    for (int o = 16; o; o >>= 1) m = fmaxf(m, __shfl_xor_sync(0xffffffffu, m, o));
    float p = __expf(acc - m);
    float s = p;
#pragma unroll
    for (int o = 16; o; o >>= 1) s += __shfl_xor_sync(0xffffffffu, s, o);
    atomicAdd(&g_sumprob[lane], p / s);

    float v = acc;
    float topv[kK]; int topi[kK];
#pragma unroll
    for (int k = 0; k < kK; ++k) {
        float bv = v; int bi = lane;
#pragma unroll
        for (int o = 16; o; o >>= 1) {
            float ov = __shfl_xor_sync(0xffffffffu, bv, o);
            int   oi = __shfl_xor_sync(0xffffffffu, bi, o);
            if (ov > bv || (ov == bv && oi < bi)) { bv = ov; bi = oi; }
        }
        topv[k] = bv; topi[k] = bi;
        if (lane == bi) v = -INFINITY;
    }

    float mx = topv[0];
    float w[kK]; float se = 0.f;
#pragma unroll
    for (int k = 0; k < kK; ++k) { w[k] = __expf(topv[k] - mx); se += w[k]; }
#pragma unroll
    for (int k = 0; k < kK; ++k) {
        if (lane == k) {
            g_topi[warp * kK + k] = topi[k];
            g_topw[warp * kK + k] = w[k] / se;
            atomicAdd(&g_counts[topi[k]], 1);
        }
    }
}

// ---------------- launch 3: offsets + aux (block0) then scatter (spin-gated) ----------------
__global__ void osa_kernel(float* __restrict__ out, int T, int out_size) {
    if (blockIdx.x == 0 && threadIdx.x == 0) {
        int s = 0;
        for (int e = 0; e < kE; ++e) { g_offsets[e] = s; s += g_counts[e]; }
        g_offsets[kE] = s;
        if ((size_t)out_size > (size_t)T * kD) {
            float a = 0.f;
            for (int e = 0; e < kE; ++e) a += g_sumprob[e] * (float)g_counts[e];
            out[(size_t)T * kD] = a / ((float)T * (float)T);
        }
        __threadfence();
        atomicExch(&g_flag, 1);
    } else {
        while (atomicAdd(&g_flag, 0) == 0) {}
    }
    __syncthreads();
    int idx = blockIdx.x * blockDim.x + threadIdx.x;
    if (idx < T * kK) {
        int e = g_topi[idx];
        int pos = g_offsets[e] + atomicAdd(&g_cursor[e], 1);
        g_rowtok[pos]   = idx / kK;
        g_rowscale[pos] = g_topw[idx];
    }
}

// =========================================================================
// GEMM1 (launch 4): 128(M) x 64(N), BK=16, 256 threads, 2 CTAs/SM, fused gate+up.
// Smem planes (pitch 48 B per 16-k row):
//   AH@0(6144) AL@6144 GH@12288(3072) GL@15360 UH@18432 UL@21504 -> 24576 B.
// SWIZZLE: element (row, quad p of 16B half) stored at quad (p + (row>>3)) & 3.
//   -> STS conflict-free (rows 8 apart get distinct rot), LDS stays conflict-free.
// =========================================================================
__global__ __launch_bounds__(256, 2) void gemm1_mma(const float* __restrict__ x,
                                                    const float* __restrict__ Wg,
                                                    const float* __restrict__ Wu) {
    __shared__ __align__(16) char sm[24576];
    __shared__ int   toks[128];
    __shared__ float scls[128];
    const int e = blockIdx.z;
    const int base  = g_offsets[e];
    const int count = g_offsets[e + 1] - base;
    const int m0 = blockIdx.y * 128;
    if (m0 >= count) return;
    const int n0 = blockIdx.x * 64;
    const int tid = threadIdx.x, lane = tid & 31, wid = tid >> 5;
    const int wm = wid & 3, wn = wid >> 2, g = lane >> 2, q = lane & 3;

    if (tid < 128) {
        int r = m0 + tid;
        toks[tid] = g_rowtok[base + ((r < count) ? r : (count - 1))];
        scls[tid] = (r < count) ? g_rowscale[base + r] : 0.f;
    }
    __syncthreads();

    const int arow = tid >> 1, ka = tid & 1;              // A: 128 rows, 2 k-halves
    const int bn = tid & 63,  kb = (tid >> 6) & 1;        // B: 64 n, 2 k-halves
    const int bmat = tid >> 7;                            // 0 = gate, 1 = up

    // swizzled store addresses (quad rotation by (row>>3)&3)
    const uint32_t oA = (uint32_t)(arow * 48 + ka * 16);
    const int rA = (arow >> 3) & 3;
    const uint32_t pa0 = oA + ((rA + 0) & 3) * 4, pa1 = oA + ((rA + 1) & 3) * 4;
    const uint32_t pa2 = oA + ((rA + 2) & 3) * 4, pa3 = oA + ((rA + 3) & 3) * 4;
    const uint32_t oB = (uint32_t)(12288 + bmat * 6144 + bn * 48 + kb * 16);
    const int rB = (bn >> 3) & 3;
    const uint32_t pb0 = oB + ((rB + 0) & 3) * 4, pb1 = oB + ((rB + 1) & 3) * 4;
    const uint32_t pb2 = oB + ((rB + 2) & 3) * 4, pb3 = oB + ((rB + 3) & 3) * 4;

    // fragment-load quad offsets: qo[i] = ((q + i) & 3) * 4
    const int qo[4] = { (q & 3) * 4, ((q + 1) & 3) * 4, ((q + 2) & 3) * 4, ((q + 3) & 3) * 4 };

    float4 ra0, ra1;
    float rb[8];

    auto load = [&](int s) {
        const int k0 = s * 16;
        const float* ap = x + (size_t)toks[arow] * kD + k0 + ka * 8;
        ra0 = *(const float4*)(ap);
        ra1 = *(const float4*)(ap + 4);
        const float* bp = (bmat ? Wu : Wg) + ((size_t)e * kD + k0 + kb * 8) * kI + n0 + bn;
#pragma unroll
        for (int i = 0; i < 8; ++i) rb[i] = bp[(size_t)i * kI];
    };
    auto store = [&]() {
        uint32_t h0, l0, h1, l1, h2, l2, h3, l3;
        pack2(ra0.x, ra0.y, h0, l0);
        pack2(ra0.z, ra0.w, h1, l1);
        pack2(ra1.x, ra1.y, h2, l2);
        pack2(ra1.z, ra1.w, h3, l3);
        *(uint32_t*)(sm + pa0) = h0;  *(uint32_t*)(sm + pa1) = h1;
        *(uint32_t*)(sm + pa2) = h2;  *(uint32_t*)(sm + pa3) = h3;
        *(uint32_t*)(sm + 6144 + pa0) = l0;  *(uint32_t*)(sm + 6144 + pa1) = l1;
        *(uint32_t*)(sm + 6144 + pa2) = l2;  *(uint32_t*)(sm + 6144 + pa3) = l3;
        pack2(rb[0], rb[1], h0, l0);
        pack2(rb[2], rb[3], h1, l1);
        pack2(rb[4], rb[5], h2, l2);
        pack2(rb[6], rb[7], h3, l3);
        *(uint32_t*)(sm + pb0) = h0;  *(uint32_t*)(sm + pb1) = h1;
        *(uint32_t*)(sm + pb2) = h2;  *(uint32_t*)(sm + pb3) = h3;
        *(uint32_t*)(sm + 3072 + pb0) = l0;  *(uint32_t*)(sm + 3072 + pb1) = l1;
        *(uint32_t*)(sm + 3072 + pb2) = l2;  *(uint32_t*)(sm + 3072 + pb3) = l3;
    };

    float cg[2][4][4] = {}, cu[2][4][4] = {};
    load(0); store();
    __syncthreads();

    const int S = kD / 16;   // 128
    for (int s = 0; s < S; ++s) {
        if (s + 1 < S) load(s + 1);
        uint32_t ah[2][4], al[2][4];
#pragma unroll
        for (int mt = 0; mt < 2; ++mt) {
            const char* o = sm + (wm * 32 + mt * 16 + g) * 48;
            const int f0 = qo[(2 * mt) & 3];
            const int f1 = qo[(2 * mt + 1) & 3];
            ah[mt][0] = *(const uint32_t*)(o + f0);
            ah[mt][1] = *(const uint32_t*)(o + 384 + f1);
            ah[mt][2] = *(const uint32_t*)(o + 16 + f0);
            ah[mt][3] = *(const uint32_t*)(o + 400 + f1);
            al[mt][0] = *(const uint32_t*)(o + 6144 + f0);
            al[mt][1] = *(const uint32_t*)(o + 6528 + f1);
            al[mt][2] = *(const uint32_t*)(o + 6160 + f0);
            al[mt][3] = *(const uint32_t*)(o + 6544 + f1);
        }
#pragma unroll
        for (int j = 0; j < 4; ++j) {
            const char* o = sm + 12288 + (wn * 32 + j * 8 + g) * 48;
            const int fj = qo[j & 3];
            uint32_t gh[2] = { *(const uint32_t*)(o + fj),          *(const uint32_t*)(o + 16 + fj) };
            uint32_t gl[2] = { *(const uint32_t*)(o + 3072 + fj),   *(const uint32_t*)(o + 3088 + fj) };
            uint32_t uh[2] = { *(const uint32_t*)(o + 6144 + fj),   *(const uint32_t*)(o + 6160 + fj) };
            uint32_t ul[2] = { *(const uint32_t*)(o + 9216 + fj),   *(const uint32_t*)(o + 9232 + fj) };
#pragma unroll
            for (int mt = 0; mt < 2; ++mt) {
                mma_bf16(cg[mt][j], ah[mt], gh);
                mma_bf16(cg[mt][j], ah[mt], gl);
                mma_bf16(cg[mt][j], al[mt], gh);
                mma_bf16(cu[mt][j], ah[mt], uh);
                mma_bf16(cu[mt][j], ah[mt], ul);
                mma_bf16(cu[mt][j], al[mt], uh);
            }
        }
        __syncthreads();
        if (s + 1 < S) store();
        __syncthreads();
    }

    // epilogue: H = silu(gate) * up * routing weight
#pragma unroll
    for (int mt = 0; mt < 2; ++mt)
#pragma unroll
        for (int h = 0; h < 2; ++h) {
            int rl = wm * 32 + mt * 16 + g + h * 8;
            if (m0 + rl < count) {
                float sc = scls[rl];
                float* dst = g_H + (size_t)(base + m0 + rl) * kI + n0 + wn * 32 + q * 2;
#pragma unroll
                for (int j = 0; j < 4; ++j) {
                    float g0 = cg[mt][j][2 * h], g1 = cg[mt][j][2 * h + 1];
                    float u0 = cu[mt][j][2 * h], u1 = cu[mt][j][2 * h + 1];
                    float h0 = g0 / (1.f + __expf(-g0)) * u0 * sc;
                    float h1 = g1 / (1.f + __expf(-g1)) * u1 * sc;
                    *(float2*)(dst + j * 8) = make_float2(h0, h1);
                }
            }
        }
}

// =========================================================================
// GEMM2 (launch 5): 128(M) x 128(N), BK=16, 256 threads, 2 CTAs/SM.
// Smem: AH@0 AL@6144 BH@12288 BL@18432 = 24576 B. Same quad-rotation swizzle.
// Warps: wm=wid&3 (32 rows), wn=wid>>2 in {0,1} (64 cols, j=0..7). atomicAdd out.
// =========================================================================
__global__ __launch_bounds__(256, 2) void gemm2_mma(float* __restrict__ out,
                                                    const float* __restrict__ Wd) {
    __shared__ __align__(16) char sm[24576];
    __shared__ int toks[128];
    const int e = blockIdx.z;
    const int base  = g_offsets[e];
    const int count = g_offsets[e + 1] - base;
    const int m0 = blockIdx.y * 128;
    if (m0 >= count) return;
    const int n0 = blockIdx.x * 128;
    const int tid = threadIdx.x, lane = tid & 31, wid = tid >> 5;
    const int wm = wid & 3, wn = wid >> 2, g = lane >> 2, q = lane & 3;

    if (tid < 128) {
        int r = m0 + tid;
        toks[tid] = g_rowtok[base + ((r < count) ? r : (count - 1))];
    }
    __syncthreads();

    const int arow = tid >> 1, ka = tid & 1;
    const int bn = tid & 127, kb = tid >> 7;
    const int arl = (m0 + arow < count) ? (m0 + arow) : (count - 1);
    const float* aptr = g_H + (size_t)(base + arl) * kI + ka * 8;

    const uint32_t oA = (uint32_t)(arow * 48 + ka * 16);
    const int rA = (arow >> 3) & 3;
    const uint32_t pa0 = oA + ((rA + 0) & 3) * 4, pa1 = oA + ((rA + 1) & 3) * 4;
    const uint32_t pa2 = oA + ((rA + 2) & 3) * 4, pa3 = oA + ((rA + 3) & 3) * 4;
    const uint32_t oB = (uint32_t)(12288 + bn * 48 + kb * 16);
    const int rB = (bn >> 3) & 3;
    const uint32_t pb0 = oB + ((rB + 0) & 3) * 4, pb1 = oB + ((rB + 1) & 3) * 4;
    const uint32_t pb2 = oB + ((rB + 2) & 3) * 4, pb3 = oB + ((rB + 3) & 3) * 4;

    const int qo[4] = { (q & 3) * 4, ((q + 1) & 3) * 4, ((q + 2) & 3) * 4, ((q + 3) & 3) * 4 };

    float4 ra0, ra1;
    float rb[8];

    auto load = [&](int s) {
        const int k0 = s * 16;
        ra0 = *(const float4*)(aptr + k0);
        ra1 = *(const float4*)(aptr + k0 + 4);
        const float* bp = Wd + ((size_t)e * kI + k0 + kb * 8) * kD + n0 + bn;
#pragma unroll
        for (int i = 0; i < 8; ++i) rb[i] = bp[(size_t)i * kD];
    };
    auto store = [&]() {
        uint32_t h0, l0, h1, l1, h2, l2, h3, l3;
        pack2(ra0.x, ra0.y, h0, l0);
        pack2(ra0.z, ra0.w, h1, l1);
        pack2(ra1.x, ra1.y, h2, l2);
        pack2(ra1.z, ra1.w, h3, l3);
        *(uint32_t*)(sm + pa0) = h0;  *(uint32_t*)(sm + pa1) = h1;
        *(uint32_t*)(sm + pa2) = h2;  *(uint32_t*)(sm + pa3) = h3;
        *(uint32_t*)(sm + 6144 + pa0) = l0;  *(uint32_t*)(sm + 6144 + pa1) = l1;
        *(uint32_t*)(sm + 6144 + pa2) = l2;  *(uint32_t*)(sm + 6144 + pa3) = l3;
        pack2(rb[0], rb[1], h0, l0);
        pack2(rb[2], rb[3], h1, l1);
        pack2(rb[4], rb[5], h2, l2);
        pack2(rb[6], rb[7], h3, l3);
        *(uint32_t*)(sm + pb0) = h0;  *(uint32_t*)(sm + pb1) = h1;
        *(uint32_t*)(sm + pb2) = h2;  *(uint32_t*)(sm + pb3) = h3;
        *(uint32_t*)(sm + 6144 + pb0) = l0;  *(uint32_t*)(sm + 6144 + pb1) = l1;
        *(uint32_t*)(sm + 6144 + pb2) = l2;  *(uint32_t*)(sm + 6144 + pb3) = l3;
    };

    float c[2][8][4] = {};
    load(0); store();
    __syncthreads();

    const int S = kI / 16;   // 64
    for (int s = 0; s < S; ++s) {
        if (s + 1 < S) load(s + 1);
        uint32_t ah[2][4], al[2][4];
#pragma unroll
        for (int mt = 0; mt < 2; ++mt) {
            const char* o = sm + (wm * 32 + mt * 16 + g) * 48;
            const int f0 = qo[(2 * mt) & 3];
            const int f1 = qo[(2 * mt + 1) & 3];
            ah[mt][0] = *(const uint32_t*)(o + f0);
            ah[mt][1] = *(const uint32_t*)(o + 384 + f1);
            ah[mt][2] = *(const uint32_t*)(o + 16 + f0);
            ah[mt][3] = *(const uint32_t*)(o + 400 + f1);
            al[mt][0] = *(const uint32_t*)(o + 6144 + f0);
            al[mt][1] = *(const uint32_t*)(o + 6528 + f1);
            al[mt][2] = *(const uint32_t*)(o + 6160 + f0);
            al[mt][3] = *(const uint32_t*)(o + 6544 + f1);
        }
#pragma unroll
        for (int j = 0; j < 8; ++j) {
            const char* o = sm + 12288 + (wn * 64 + j * 8 + g) * 48;
            const int fj = qo[j & 3];
            uint32_t bh[2] = { *(const uint32_t*)(o + fj),        *(const uint32_t*)(o + 16 + fj) };
            uint32_t bl[2] = { *(const uint32_t*)(o + 6144 + fj), *(const uint32_t*)(o + 6160 + fj) };
#pragma unroll
            for (int mt = 0; mt < 2; ++mt) {
                mma_bf16(c[mt][j], ah[mt], bh);
                mma_bf16(c[mt][j], ah[mt], bl);
                mma_bf16(c[mt][j], al[mt], bh);
            }
        }
        __syncthreads();
        if (s + 1 < S) store();
        __syncthreads();
    }

#pragma unroll
    for (int mt = 0; mt < 2; ++mt)
#pragma unroll
        for (int h = 0; h < 2; ++h) {
            int rl = wm * 32 + mt * 16 + g + h * 8;
            if (m0 + rl < count) {
                int tok = toks[rl];
                float* op = out + (size_t)tok * kD + n0 + wn * 64 + q * 2;
#pragma unroll
                for (int j = 0; j < 8; ++j) {
                    atomicAdd(&op[j * 8],     c[mt][j][2 * h]);
                    atomicAdd(&op[j * 8 + 1], c[mt][j][2 * h + 1]);
                }
            }
        }
}

// ---------------- launch ----------------
extern "C" void kernel_launch(void* const* d_in, const int* in_sizes, int n_in,
                              void* d_out, int out_size) {
    const float* x     = (const float*)d_in[0];
    const float* Wgate = (const float*)d_in[1];
    const float* Wg    = (const float*)d_in[2];
    const float* Wu    = (const float*)d_in[3];
    const float* Wd    = (const float*)d_in[4];
    float* out = (float*)d_out;

    const int T = in_sizes[0] / kD;

    zeroreset_kernel<<<2048, 256>>>(out, (size_t)out_size);           // launch 1
    router_kernel<<<(T + 7) / 8, 256>>>(x, Wgate, T);                 // launch 2
    osa_kernel<<<(T * kK + 255) / 256, 256>>>(out, T, out_size);      // launch 3
    gemm1_mma<<<dim3(kI / 64, kMaxT / 128, kE), 256>>>(x, Wg, Wu);    // launch 4
    gemm2_mma<<<dim3(kD / 128, kMaxT / 128, kE), 256>>>(out, Wd);     // launch 5
}

// round 13
// speedup vs baseline: 1.0923x; 1.0923x over previous
#include <cuda_runtime.h>
#include <cuda_bf16.h>
#include <math.h>
#include <stdint.h>

constexpr int kD = 2048, kE = 32, kK = 8, kI = 1024, kMaxT = 8192;
constexpr int kMaxRows = kMaxT * kK;   // 65536

// ---------------- scratch (proven-size set; DO NOT grow) ----------------
__device__ int   g_topi[kMaxRows];
__device__ float g_topw[kMaxRows];
__device__ int   g_rowtok[kMaxRows];
__device__ float g_rowscale[kMaxRows];
__device__ int   g_counts[kE];
__device__ int   g_offsets[kE + 1];
__device__ int   g_cursor[kE];
__device__ float g_sumprob[kE];
__device__ int   g_flag;
__device__ __align__(16) float g_H[(size_t)kMaxRows * kI];   // 256 MB scratch

// ---------------- helpers ----------------
__device__ __forceinline__ void mma_bf16(float* c, const uint32_t* a, const uint32_t* b) {
    asm volatile(
        "mma.sync.aligned.m16n8k16.row.col.f32.bf16.bf16.f32 "
        "{%0,%1,%2,%3}, {%4,%5,%6,%7}, {%8,%9}, {%0,%1,%2,%3};"
        : "+f"(c[0]), "+f"(c[1]), "+f"(c[2]), "+f"(c[3])
        : "r"(a[0]), "r"(a[1]), "r"(a[2]), "r"(a[3]), "r"(b[0]), "r"(b[1]));
}
// Truncation-based hi/lo split of a float pair, packed as bf16x2.
__device__ __forceinline__ void pack2(float a, float b, uint32_t& hi, uint32_t& lo) {
    uint32_t ra = __float_as_uint(a), rb = __float_as_uint(b);
    asm("prmt.b32 %0, %1, %2, 0x7632;" : "=r"(hi) : "r"(ra), "r"(rb));
    float la = a - __uint_as_float(ra & 0xFFFF0000u);
    float lb = b - __uint_as_float(rb & 0xFFFF0000u);
    asm("prmt.b32 %0, %1, %2, 0x7632;" : "=r"(lo) : "r"(__float_as_uint(la)), "r"(__float_as_uint(lb)));
}

// ---------------- launch 1: zero out + reset bookkeeping ----------------
__global__ void zeroreset_kernel(float* __restrict__ out, size_t n) {
    size_t i = (size_t)blockIdx.x * blockDim.x + threadIdx.x;
    size_t stride = (size_t)gridDim.x * blockDim.x;
    for (; i < n; i += stride) out[i] = 0.f;
    if (blockIdx.x == 0) {
        if (threadIdx.x < kE) {
            g_counts[threadIdx.x] = 0;
            g_cursor[threadIdx.x] = 0;
            g_sumprob[threadIdx.x] = 0.f;
        }
        if (threadIdx.x == 0) g_flag = 0;
    }
}

// ---------------- launch 2: router ----------------
__global__ void router_kernel(const float* __restrict__ x,
                              const float* __restrict__ Wgate, int T) {
    int warp = (blockIdx.x * blockDim.x + threadIdx.x) >> 5;
    int lane = threadIdx.x & 31;
    if (warp >= T) return;
    const float* xt = x + (size_t)warp * kD;

    float acc = 0.f;
#pragma unroll 4
    for (int d = 0; d < kD; ++d) acc += xt[d] * Wgate[d * kE + lane];

    float m = acc;
#pragma unroll
    for (int o = 16; o; o >>= 1) m = fmaxf(m, __shfl_xor_sync(0xffffffffu, m, o));
    float p = __expf(acc - m);
    float s = p;
#pragma unroll
    for (int o = 16; o; o >>= 1) s += __shfl_xor_sync(0xffffffffu, s, o);
    atomicAdd(&g_sumprob[lane], p / s);

    float v = acc;
    float topv[kK]; int topi[kK];
#pragma unroll
    for (int k = 0; k < kK; ++k) {
        float bv = v; int bi = lane;
#pragma unroll
        for (int o = 16; o; o >>= 1) {
            float ov = __shfl_xor_sync(0xffffffffu, bv, o);
            int   oi = __shfl_xor_sync(0xffffffffu, bi, o);
            if (ov > bv || (ov == bv && oi < bi)) { bv = ov; bi = oi; }
        }
        topv[k] = bv; topi[k] = bi;
        if (lane == bi) v = -INFINITY;
    }

    float mx = topv[0];
    float w[kK]; float se = 0.f;
#pragma unroll
    for (int k = 0; k < kK; ++k) { w[k] = __expf(topv[k] - mx); se += w[k]; }
#pragma unroll
    for (int k = 0; k < kK; ++k) {
        if (lane == k) {
            g_topi[warp * kK + k] = topi[k];
            g_topw[warp * kK + k] = w[k] / se;
            atomicAdd(&g_counts[topi[k]], 1);
        }
    }
}

// ---------------- launch 3: offsets + aux (block0) then scatter (spin-gated) ----------------
__global__ void osa_kernel(float* __restrict__ out, int T, int out_size) {
    if (blockIdx.x == 0 && threadIdx.x == 0) {
        int s = 0;
        for (int e = 0; e < kE; ++e) { g_offsets[e] = s; s += g_counts[e]; }
        g_offsets[kE] = s;
        if ((size_t)out_size > (size_t)T * kD) {
            float a = 0.f;
            for (int e = 0; e < kE; ++e) a += g_sumprob[e] * (float)g_counts[e];
            out[(size_t)T * kD] = a / ((float)T * (float)T);
        }
        __threadfence();
        atomicExch(&g_flag, 1);
    } else {
        while (atomicAdd(&g_flag, 0) == 0) {}
    }
    __syncthreads();
    int idx = blockIdx.x * blockDim.x + threadIdx.x;
    if (idx < T * kK) {
        int e = g_topi[idx];
        int pos = g_offsets[e] + atomicAdd(&g_cursor[e], 1);
        g_rowtok[pos]   = idx / kK;
        g_rowscale[pos] = g_topw[idx];
    }
}

// =========================================================================
// GEMM1 (launch 4): 128(M) x 64(N), BK=16, 256 threads, 2 CTAs/SM, fused gate+up.
// DOUBLE-BUFFERED dynamic smem, ONE sync per stage:
//   stage = 24576 B: AH@0(6144) AL@6144 GH@12288(3072) GL@15360 UH@18432 UL@21504
// Pipeline: load_regs(s+1) -> compute(buf) -> store(buf^1) -> sync -> flip.
// Warps: wm=wid&3 (32 rows), wn=wid>>2 in {0,1}. R10-proven fragment map.
// =========================================================================
constexpr int G1_STG = 24576;
__global__ __launch_bounds__(256, 2) void gemm1_mma(const float* __restrict__ x,
                                                    const float* __restrict__ Wg,
                                                    const float* __restrict__ Wu) {
    extern __shared__ __align__(16) char sm[];
    __shared__ int   toks[128];
    __shared__ float scls[128];
    const int e = blockIdx.z;
    const int base  = g_offsets[e];
    const int count = g_offsets[e + 1] - base;
    const int m0 = blockIdx.y * 128;
    if (m0 >= count) return;
    const int n0 = blockIdx.x * 64;
    const int tid = threadIdx.x, lane = tid & 31, wid = tid >> 5;
    const int wm = wid & 3, wn = wid >> 2, g = lane >> 2, q = lane & 3;

    if (tid < 128) {
        int r = m0 + tid;
        toks[tid] = g_rowtok[base + ((r < count) ? r : (count - 1))];
        scls[tid] = (r < count) ? g_rowscale[base + r] : 0.f;
    }
    __syncthreads();

    const int arow = tid >> 1, ah8 = (tid & 1) * 8;       // A: 128 rows, 8-k halves
    const int bn = tid & 63, bk8 = ((tid >> 6) & 1) * 8;  // B: 64 n, 8-k halves
    const int bmat = tid >> 7;                             // 0 = gate, 1 = up

    float4 ra0, ra1;
    float rb[8];

    auto load = [&](int s) {
        const int k0 = s * 16;
        const float* ap = x + (size_t)toks[arow] * kD + k0 + ah8;
        ra0 = *(const float4*)(ap);
        ra1 = *(const float4*)(ap + 4);
        const float* bp = (bmat ? Wu : Wg) + ((size_t)e * kD + k0 + bk8) * kI + n0 + bn;
#pragma unroll
        for (int i = 0; i < 8; ++i) rb[i] = bp[(size_t)i * kI];
    };
    auto store = [&](int buf) {
        char* bb = sm + buf * G1_STG;
        uint32_t h0, l0, h1, l1, h2, l2, h3, l3;
        {
            uint32_t o = (uint32_t)(arow * 48 + ah8 * 2);
            pack2(ra0.x, ra0.y, h0, l0);
            pack2(ra0.z, ra0.w, h1, l1);
            pack2(ra1.x, ra1.y, h2, l2);
            pack2(ra1.z, ra1.w, h3, l3);
            *(uint32_t*)(bb + o)             = h0;
            *(uint32_t*)(bb + o + 4)         = h1;
            *(uint32_t*)(bb + o + 8)         = h2;
            *(uint32_t*)(bb + o + 12)        = h3;
            *(uint32_t*)(bb + 6144 + o)      = l0;
            *(uint32_t*)(bb + 6144 + o + 4)  = l1;
            *(uint32_t*)(bb + 6144 + o + 8)  = l2;
            *(uint32_t*)(bb + 6144 + o + 12) = l3;
        }
        {
            uint32_t bofs = 12288 + (uint32_t)bmat * 6144;
            uint32_t o = (uint32_t)(bn * 48 + bk8 * 2);
            pack2(rb[0], rb[1], h0, l0);
            pack2(rb[2], rb[3], h1, l1);
            pack2(rb[4], rb[5], h2, l2);
            pack2(rb[6], rb[7], h3, l3);
            *(uint32_t*)(bb + bofs + o)             = h0;
            *(uint32_t*)(bb + bofs + o + 4)         = h1;
            *(uint32_t*)(bb + bofs + o + 8)         = h2;
            *(uint32_t*)(bb + bofs + o + 12)        = h3;
            *(uint32_t*)(bb + bofs + 3072 + o)      = l0;
            *(uint32_t*)(bb + bofs + 3072 + o + 4)  = l1;
            *(uint32_t*)(bb + bofs + 3072 + o + 8)  = l2;
            *(uint32_t*)(bb + bofs + 3072 + o + 12) = l3;
        }
    };

    float cg[2][4][4] = {}, cu[2][4][4] = {};
    load(0); store(0);
    __syncthreads();

    const int S = kD / 16;   // 128
    int buf = 0;
    for (int s = 0; s < S; ++s) {
        if (s + 1 < S) load(s + 1);
        const char* bb = sm + buf * G1_STG;
        uint32_t ah[2][4], al[2][4];
#pragma unroll
        for (int mt = 0; mt < 2; ++mt) {
            const char* o = bb + (wm * 32 + mt * 16 + g) * 48 + q * 4;
            ah[mt][0] = *(const uint32_t*)(o);
            ah[mt][1] = *(const uint32_t*)(o + 384);
            ah[mt][2] = *(const uint32_t*)(o + 16);
            ah[mt][3] = *(const uint32_t*)(o + 400);
            al[mt][0] = *(const uint32_t*)(o + 6144);
            al[mt][1] = *(const uint32_t*)(o + 6528);
            al[mt][2] = *(const uint32_t*)(o + 6160);
            al[mt][3] = *(const uint32_t*)(o + 6544);
        }
#pragma unroll
        for (int j = 0; j < 4; ++j) {
            const char* o = bb + 12288 + (wn * 32 + j * 8 + g) * 48 + q * 4;
            uint32_t gh[2] = { *(const uint32_t*)(o),         *(const uint32_t*)(o + 16) };
            uint32_t gl[2] = { *(const uint32_t*)(o + 3072),  *(const uint32_t*)(o + 3088) };
            uint32_t uh[2] = { *(const uint32_t*)(o + 6144),  *(const uint32_t*)(o + 6160) };
            uint32_t ul[2] = { *(const uint32_t*)(o + 9216),  *(const uint32_t*)(o + 9232) };
#pragma unroll
            for (int mt = 0; mt < 2; ++mt) {
                mma_bf16(cg[mt][j], ah[mt], gh);
                mma_bf16(cg[mt][j], ah[mt], gl);
                mma_bf16(cg[mt][j], al[mt], gh);
                mma_bf16(cu[mt][j], ah[mt], uh);
                mma_bf16(cu[mt][j], ah[mt], ul);
                mma_bf16(cu[mt][j], al[mt], uh);
            }
        }
        if (s + 1 < S) store(buf ^ 1);
        __syncthreads();
        buf ^= 1;
    }

    // epilogue: H = silu(gate) * up * routing weight
#pragma unroll
    for (int mt = 0; mt < 2; ++mt)
#pragma unroll
        for (int h = 0; h < 2; ++h) {
            int rl = wm * 32 + mt * 16 + g + h * 8;
            if (m0 + rl < count) {
                float sc = scls[rl];
                float* dst = g_H + (size_t)(base + m0 + rl) * kI + n0 + wn * 32 + q * 2;
#pragma unroll
                for (int j = 0; j < 4; ++j) {
                    float g0 = cg[mt][j][2 * h], g1 = cg[mt][j][2 * h + 1];
                    float u0 = cu[mt][j][2 * h], u1 = cu[mt][j][2 * h + 1];
                    float h0 = g0 / (1.f + __expf(-g0)) * u0 * sc;
                    float h1 = g1 / (1.f + __expf(-g1)) * u1 * sc;
                    *(float2*)(dst + j * 8) = make_float2(h0, h1);
                }
            }
        }
}

// =========================================================================
// GEMM2 (launch 5): 128(M) x 128(N), BK=16, 256 threads, 2 CTAs/SM.
// DOUBLE-BUFFERED dynamic smem, ONE sync per stage.
//   stage = 24576 B: AH@0 AL@6144 BH@12288 BL@18432. atomicAdd epilogue.
// =========================================================================
constexpr int G2_STG = 24576;
__global__ __launch_bounds__(256, 2) void gemm2_mma(float* __restrict__ out,
                                                    const float* __restrict__ Wd) {
    extern __shared__ __align__(16) char sm[];
    __shared__ int toks[128];
    const int e = blockIdx.z;
    const int base  = g_offsets[e];
    const int count = g_offsets[e + 1] - base;
    const int m0 = blockIdx.y * 128;
    if (m0 >= count) return;
    const int n0 = blockIdx.x * 128;
    const int tid = threadIdx.x, lane = tid & 31, wid = tid >> 5;
    const int wm = wid & 3, wn = wid >> 2, g = lane >> 2, q = lane & 3;

    if (tid < 128) {
        int r = m0 + tid;
        toks[tid] = g_rowtok[base + ((r < count) ? r : (count - 1))];
    }
    __syncthreads();

    const int arow = tid >> 1, ah8 = (tid & 1) * 8;
    const int bn = tid & 127, bk8 = (tid >> 7) * 8;
    const int arl = (m0 + arow < count) ? (m0 + arow) : (count - 1);
    const float* aptr = g_H + (size_t)(base + arl) * kI + ah8;

    float4 ra0, ra1;
    float rb[8];

    auto load = [&](int s) {
        const int k0 = s * 16;
        ra0 = *(const float4*)(aptr + k0);
        ra1 = *(const float4*)(aptr + k0 + 4);
        const float* bp = Wd + ((size_t)e * kI + k0 + bk8) * kD + n0 + bn;
#pragma unroll
        for (int i = 0; i < 8; ++i) rb[i] = bp[(size_t)i * kD];
    };
    auto store = [&](int buf) {
        char* bb = sm + buf * G2_STG;
        uint32_t h0, l0, h1, l1, h2, l2, h3, l3;
        {
            uint32_t o = (uint32_t)(arow * 48 + ah8 * 2);
            pack2(ra0.x, ra0.y, h0, l0);
            pack2(ra0.z, ra0.w, h1, l1);
            pack2(ra1.x, ra1.y, h2, l2);
            pack2(ra1.z, ra1.w, h3, l3);
            *(uint32_t*)(bb + o)             = h0;
            *(uint32_t*)(bb + o + 4)         = h1;
            *(uint32_t*)(bb + o + 8)         = h2;
            *(uint32_t*)(bb + o + 12)        = h3;
            *(uint32_t*)(bb + 6144 + o)      = l0;
            *(uint32_t*)(bb + 6144 + o + 4)  = l1;
            *(uint32_t*)(bb + 6144 + o + 8)  = l2;
            *(uint32_t*)(bb + 6144 + o + 12) = l3;
        }
        {
            uint32_t o = (uint32_t)(bn * 48 + bk8 * 2);
            pack2(rb[0], rb[1], h0, l0);
            pack2(rb[2], rb[3], h1, l1);
            pack2(rb[4], rb[5], h2, l2);
            pack2(rb[6], rb[7], h3, l3);
            *(uint32_t*)(bb + 12288 + o)      = h0;
            *(uint32_t*)(bb + 12288 + o + 4)  = h1;
            *(uint32_t*)(bb + 12288 + o + 8)  = h2;
            *(uint32_t*)(bb + 12288 + o + 12) = h3;
            *(uint32_t*)(bb + 18432 + o)      = l0;
            *(uint32_t*)(bb + 18432 + o + 4)  = l1;
            *(uint32_t*)(bb + 18432 + o + 8)  = l2;
            *(uint32_t*)(bb + 18432 + o + 12) = l3;
        }
    };

    float c[2][8][4] = {};
    load(0); store(0);
    __syncthreads();

    const int S = kI / 16;   // 64
    int buf = 0;
    for (int s = 0; s < S; ++s) {
        if (s + 1 < S) load(s + 1);
        const char* bb = sm + buf * G2_STG;
        uint32_t ah[2][4], al[2][4];
#pragma unroll
        for (int mt = 0; mt < 2; ++mt) {
            const char* o = bb + (wm * 32 + mt * 16 + g) * 48 + q * 4;
            ah[mt][0] = *(const uint32_t*)(o);
            ah[mt][1] = *(const uint32_t*)(o + 384);
            ah[mt][2] = *(const uint32_t*)(o + 16);
            ah[mt][3] = *(const uint32_t*)(o + 400);
            al[mt][0] = *(const uint32_t*)(o + 6144);
            al[mt][1] = *(const uint32_t*)(o + 6528);
            al[mt][2] = *(const uint32_t*)(o + 6160);
            al[mt][3] = *(const uint32_t*)(o + 6544);
        }
#pragma unroll
        for (int j = 0; j < 8; ++j) {
            const char* o = bb + 12288 + (wn * 64 + j * 8 + g) * 48 + q * 4;
            uint32_t bh[2] = { *(const uint32_t*)(o),        *(const uint32_t*)(o + 16) };
            uint32_t bl[2] = { *(const uint32_t*)(o + 6144), *(const uint32_t*)(o + 6160) };
#pragma unroll
            for (int mt = 0; mt < 2; ++mt) {
                mma_bf16(c[mt][j], ah[mt], bh);
                mma_bf16(c[mt][j], ah[mt], bl);
                mma_bf16(c[mt][j], al[mt], bh);
            }
        }
        if (s + 1 < S) store(buf ^ 1);
        __syncthreads();
        buf ^= 1;
    }

#pragma unroll
    for (int mt = 0; mt < 2; ++mt)
#pragma unroll
        for (int h = 0; h < 2; ++h) {
            int rl = wm * 32 + mt * 16 + g + h * 8;
            if (m0 + rl < count) {
                int tok = toks[rl];
                float* op = out + (size_t)tok * kD + n0 + wn * 64 + q * 2;
#pragma unroll
                for (int j = 0; j < 8; ++j) {
                    atomicAdd(&op[j * 8],     c[mt][j][2 * h]);
                    atomicAdd(&op[j * 8 + 1], c[mt][j][2 * h + 1]);
                }
            }
        }
}

// ---------------- launch ----------------
extern "C" void kernel_launch(void* const* d_in, const int* in_sizes, int n_in,
                              void* d_out, int out_size) {
    const float* x     = (const float*)d_in[0];
    const float* Wgate = (const float*)d_in[1];
    const float* Wg    = (const float*)d_in[2];
    const float* Wu    = (const float*)d_in[3];
    const float* Wd    = (const float*)d_in[4];
    float* out = (float*)d_out;

    const int T = in_sizes[0] / kD;

    cudaFuncSetAttribute(gemm1_mma, cudaFuncAttributeMaxDynamicSharedMemorySize, 2 * G1_STG);
    cudaFuncSetAttribute(gemm2_mma, cudaFuncAttributeMaxDynamicSharedMemorySize, 2 * G2_STG);

    zeroreset_kernel<<<2048, 256>>>(out, (size_t)out_size);                 // launch 1
    router_kernel<<<(T + 7) / 8, 256>>>(x, Wgate, T);                       // launch 2
    osa_kernel<<<(T * kK + 255) / 256, 256>>>(out, T, out_size);            // launch 3
    gemm1_mma<<<dim3(kI / 64, kMaxT / 128, kE), 256, 2 * G1_STG>>>(x, Wg, Wu);   // launch 4
    gemm2_mma<<<dim3(kD / 128, kMaxT / 128, kE), 256, 2 * G2_STG>>>(out, Wd);    // launch 5
}